// round 14
// baseline (speedup 1.0000x reference)
#include <cuda_runtime.h>
#include <cuda_bf16.h>
#include <cstdint>

#define HWN 1024
#define CDIM 128
#define EXPD 512
#define NB   16

// Scratch (allocation-free rule: static __device__ arrays)
__device__ __align__(128) __nv_bfloat16 g_q[NB * EXPD * HWN]; // [b][h][n][d]
__device__ __align__(128) __nv_bfloat16 g_k[NB * EXPD * HWN]; // [b][h][m][d]
__device__ __align__(128) __nv_bfloat16 g_v[NB * EXPD * HWN]; // [b][h][d][m]
__device__ __align__(128) __nv_bfloat16 g_wsv[NB * EXPD * HWN]; // bf16 [b][c'][pix]
__device__ __align__(128) __nv_bfloat16 g_xb[NB * HWN * CDIM];  // x^T bf16 [b][n][c]
__device__ __align__(128) __nv_bfloat16 g_wqb[EXPD * CDIM];
__device__ __align__(128) __nv_bfloat16 g_wkb[EXPD * CDIM];
__device__ __align__(128) __nv_bfloat16 g_wvb[EXPD * CDIM];
__device__ __align__(128) __nv_bfloat16 g_wtb[CDIM * EXPD];

// ---------------------------------------------------------------------------
__device__ __forceinline__ uint32_t smem_u32(const void* p) {
    uint32_t a;
    asm("{ .reg .u64 t; cvta.to.shared.u64 t, %1; cvt.u32.u64 %0, t; }"
        : "=r"(a) : "l"(p));
    return a;
}

__device__ __forceinline__ void cpa16(uint32_t dst, const void* src) {
    asm volatile("cp.async.ca.shared.global [%0], [%1], 16;"
                 :: "r"(dst), "l"(src));
}
#define CP_COMMIT() asm volatile("cp.async.commit_group;")
#define CP_WAIT0()  asm volatile("cp.async.wait_group 0;")
#define CP_WAIT1()  asm volatile("cp.async.wait_group 1;")

// bf16 m16n8k16 mma
__device__ __forceinline__ void mma16(float (&d)[4], const uint32_t (&a)[4],
                                      uint32_t b0, uint32_t b1) {
    asm volatile(
        "mma.sync.aligned.m16n8k16.row.col.f32.bf16.bf16.f32 "
        "{%0,%1,%2,%3}, {%4,%5,%6,%7}, {%8,%9}, {%0,%1,%2,%3};"
        : "+f"(d[0]), "+f"(d[1]), "+f"(d[2]), "+f"(d[3])
        : "r"(a[0]), "r"(a[1]), "r"(a[2]), "r"(a[3]), "r"(b0), "r"(b1));
}

__device__ __forceinline__ void ldsm4(uint32_t (&r)[4], uint32_t addr) {
    asm volatile("ldmatrix.sync.aligned.m8n8.x4.shared.b16 {%0,%1,%2,%3}, [%4];"
                 : "=r"(r[0]), "=r"(r[1]), "=r"(r[2]), "=r"(r[3]) : "r"(addr));
}
__device__ __forceinline__ void ldsm4t(uint32_t (&r)[4], uint32_t addr) {
    asm volatile("ldmatrix.sync.aligned.m8n8.x4.trans.shared.b16 {%0,%1,%2,%3}, [%4];"
                 : "=r"(r[0]), "=r"(r[1]), "=r"(r[2]), "=r"(r[3]) : "r"(addr));
}

__device__ __forceinline__ uint32_t packbf(float lo, float hi) {
    uint32_t d;
    asm("cvt.rn.bf16x2.f32 %0, %1, %2;" : "=r"(d) : "f"(hi), "f"(lo));
    return d;
}

__device__ __forceinline__ float ex2a(float x) {
    float r;
    asm("ex2.approx.ftz.f32 %0, %1;" : "=f"(r) : "f"(x));
    return r;
}

// ---------------------------------------------------------------------------
// All four weight conversions in ONE launch.
__global__ __launch_bounds__(256) void cvt_all(
    const float* __restrict__ s0, const float* __restrict__ s1,
    const float* __restrict__ s2, const float* __restrict__ s3,
    __nv_bfloat16* __restrict__ d0, __nv_bfloat16* __restrict__ d1,
    __nv_bfloat16* __restrict__ d2, __nv_bfloat16* __restrict__ d3)
{
    const int seg = blockIdx.x >> 7;
    const int i = ((blockIdx.x & 127) * 256 + threadIdx.x) * 2;
    const float* s = (seg == 0) ? s0 : (seg == 1) ? s1 : (seg == 2) ? s2 : s3;
    __nv_bfloat16* d = (seg == 0) ? d0 : (seg == 1) ? d1 : (seg == 2) ? d2 : d3;
    float2 v = *(const float2*)&s[i];
    *(uint32_t*)&d[i] = packbf(v.x, v.y);
}

// x[z][c][n] f32 -> xb[z][n][c] bf16 (32x32 smem-tile transpose)
__global__ __launch_bounds__(256) void xpose(
    const float* __restrict__ x, __nv_bfloat16* __restrict__ xb)
{
    __shared__ float ts[32][33];
    const int z = blockIdx.z;
    const int nx = blockIdx.x * 32, cy = blockIdx.y * 32;
    const int tx = threadIdx.x & 31, ty = threadIdx.x >> 5;
#pragma unroll
    for (int i = 0; i < 4; i++) {
        int c = cy + ty + i * 8;
        ts[ty + i * 8][tx] = x[((size_t)z * CDIM + c) * HWN + nx + tx];
    }
    __syncthreads();
#pragma unroll
    for (int i = 0; i < 4; i++) {
        int n = nx + ty + i * 8;
        xb[((size_t)z * HWN + n) * CDIM + cy + tx] =
            __float2bfloat16(ts[tx][ty + i * 8]);
    }
}

// ---------------------------------------------------------------------------
// Fused QKV GEMM, bf16 m16n8k16, ldmatrix. CTA tile 64(o) x 128(n). (R13)
// ---------------------------------------------------------------------------
__global__ __launch_bounds__(256) void gemm_qkv(
    const __nv_bfloat16* __restrict__ xb,
    const __nv_bfloat16* __restrict__ Wqb, const __nv_bfloat16* __restrict__ Wkb,
    const __nv_bfloat16* __restrict__ Wvb, const float* __restrict__ bv,
    __nv_bfloat16* __restrict__ qo, __nv_bfloat16* __restrict__ ko,
    __nv_bfloat16* __restrict__ vo)
{
    extern __shared__ __nv_bfloat16 sb[];
    __nv_bfloat16* Xs = sb;                          // [128][136]
    __nv_bfloat16* WsA[2] = {sb + 17408, sb + 26112};// [64][136] each
    const uint32_t xs_a = smem_u32(Xs);
    const uint32_t ws_a[2] = {smem_u32(WsA[0]), smem_u32(WsA[1])};

    const int z = blockIdx.z;
    const int n0 = blockIdx.x * 128;
    const int o0 = blockIdx.y * 64;
    const int tid = threadIdx.x;
    const int w = tid >> 5, lane = tid & 31;
    const int g = lane >> 2, t = lane & 3;
    const int wo = w >> 2, wn = w & 3;
    const int l7 = lane & 7, mi = lane >> 3;

    uint32_t a_off[2], b_off[2];
#pragma unroll
    for (int i = 0; i < 2; i++)
        a_off[i] = (uint32_t)((wo * 32 + i * 16 + (mi & 1) * 8 + l7) * 272
                              + (mi >> 1) * 16);
#pragma unroll
    for (int i = 0; i < 2; i++)
        b_off[i] = (uint32_t)((wn * 32 + i * 16 + (mi >> 1) * 8 + l7) * 272
                              + (mi & 1) * 16);

    const __nv_bfloat16* Wmat[3] = {Wqb, Wkb, Wvb};
    const __nv_bfloat16* xrow = xb + ((size_t)z * HWN + n0) * CDIM;

#pragma unroll
    for (int p = 0; p < 8; p++) {
        int idx = tid + p * 256;
        int r = idx >> 4, c = idx & 15;
        cpa16(xs_a + (uint32_t)(r * 272 + c * 16), &xrow[(size_t)r * CDIM + c * 8]);
    }
#pragma unroll
    for (int p = 0; p < 4; p++) {
        int idx = tid + p * 256;
        int r = idx >> 4, c = idx & 15;
        cpa16(ws_a[0] + (uint32_t)(r * 272 + c * 16),
              &Wqb[(size_t)(o0 + r) * CDIM + c * 8]);
    }
    CP_COMMIT();

    for (int mat = 0; mat < 3; mat++) {
        if (mat < 2) {
            const __nv_bfloat16* Wn = Wmat[mat + 1];
#pragma unroll
            for (int p = 0; p < 4; p++) {
                int idx = tid + p * 256;
                int r = idx >> 4, c = idx & 15;
                cpa16(ws_a[(mat + 1) & 1] + (uint32_t)(r * 272 + c * 16),
                      &Wn[(size_t)(o0 + r) * CDIM + c * 8]);
            }
            CP_COMMIT();
            CP_WAIT1();
        } else {
            CP_WAIT0();
        }
        __syncthreads();

        const uint32_t wcur = ws_a[mat & 1];
        float acc[2][4][4] = {};
#pragma unroll
        for (int kk = 0; kk < 8; kk++) {
            uint32_t a0[4], a1[4], b0[4], b1[4];
            ldsm4(a0, wcur + a_off[0] + kk * 32);
            ldsm4(a1, wcur + a_off[1] + kk * 32);
            ldsm4(b0, xs_a + b_off[0] + kk * 32);
            ldsm4(b1, xs_a + b_off[1] + kk * 32);
            mma16(acc[0][0], a0, b0[0], b0[1]);
            mma16(acc[0][1], a0, b0[2], b0[3]);
            mma16(acc[0][2], a0, b1[0], b1[1]);
            mma16(acc[0][3], a0, b1[2], b1[3]);
            mma16(acc[1][0], a1, b0[0], b0[1]);
            mma16(acc[1][1], a1, b0[2], b0[3]);
            mma16(acc[1][2], a1, b1[0], b1[1]);
            mma16(acc[1][3], a1, b1[2], b1[3]);
        }
        __syncthreads();

        if (mat < 2) {
            __nv_bfloat16* C = (mat == 0) ? qo : ko;
            const int head = o0 >> 7, d0 = o0 & 127;
            float* Cs = (float*)WsA[mat & 1];
#pragma unroll
            for (int hh = 0; hh < 2; hh++) {
                if ((wn >> 1) == hh) {
#pragma unroll
                    for (int i = 0; i < 2; i++) {
                        int ol = wo * 32 + i * 16 + g;
#pragma unroll
                        for (int j = 0; j < 4; j++) {
                            int nl = (wn & 1) * 32 + j * 8 + 2 * t;
                            Cs[nl * 68 + ol]           = acc[i][j][0];
                            Cs[(nl + 1) * 68 + ol]     = acc[i][j][1];
                            Cs[nl * 68 + ol + 8]       = acc[i][j][2];
                            Cs[(nl + 1) * 68 + ol + 8] = acc[i][j][3];
                        }
                    }
                }
                __syncthreads();
#pragma unroll
                for (int p = 0; p < 4; p++) {
                    int idx = p * 256 + tid;
                    int nl = idx >> 4, o4 = (idx & 15) * 4;
                    float4 vv = *(float4*)&Cs[nl * 68 + o4];
                    uint2 pk = make_uint2(packbf(vv.x, vv.y), packbf(vv.z, vv.w));
                    *(uint2*)&C[(((size_t)z * 4 + head) * HWN + n0 + hh * 64 + nl)
                                * CDIM + d0 + o4] = pk;
                }
                __syncthreads();
            }
        } else {
#pragma unroll
            for (int i = 0; i < 2; i++) {
                int ob = o0 + wo * 32 + i * 16 + g;
#pragma unroll
                for (int rr = 0; rr < 2; rr++) {
                    int orow = ob + rr * 8;
                    float bi = bv[orow];
#pragma unroll
                    for (int j = 0; j < 4; j++) {
                        int n = n0 + wn * 32 + j * 8 + 2 * t;
                        size_t addr = (size_t)z * EXPD * HWN + (size_t)orow * HWN + n;
                        *(uint32_t*)&vo[addr] = packbf(acc[i][j][rr * 2 + 0] + bi,
                                                       acc[i][j][rr * 2 + 1] + bi);
                    }
                }
            }
        }
    }
}

// ---------------------------------------------------------------------------
// Projection GEMM, bf16 m16n8k16 (unchanged).
// ---------------------------------------------------------------------------
__global__ __launch_bounds__(256) void gemm_proj(
    const __nv_bfloat16* __restrict__ A, const __nv_bfloat16* __restrict__ Bbase,
    const float* __restrict__ bias, const float* __restrict__ resid,
    float* __restrict__ C)
{
    extern __shared__ __nv_bfloat16 sb[];
    __nv_bfloat16* Ws = sb;            // [64][136]
    __nv_bfloat16* Xs = sb + 8704;     // [128][72]
    const uint32_t ws_a = smem_u32(Ws), xs_a = smem_u32(Xs);

    const int z = blockIdx.z;
    const __nv_bfloat16* B = Bbase + (size_t)z * EXPD * HWN;
    const int n0 = blockIdx.x * 64;
    const int o0 = blockIdx.y * 64;
    const int tid = threadIdx.x;
    const int w = tid >> 5, lane = tid & 31;
    const int g = lane >> 2, t = lane & 3;
    const int wo = w >> 2, wn = w & 3;
    const int l7 = lane & 7, mi = lane >> 3;

    uint32_t a_off[2];
#pragma unroll
    for (int i = 0; i < 2; i++)
        a_off[i] = (uint32_t)((wo * 32 + i * 16 + (mi & 1) * 8 + l7) * 272
                              + (mi >> 1) * 16);
    const uint32_t b_off = (uint32_t)(((mi & 1) * 8 + l7) * 144
                                      + (wn * 16 + (mi >> 1) * 8) * 2);

    float acc[2][2][4] = {};

    for (int k0 = 0; k0 < EXPD; k0 += 128) {
#pragma unroll
        for (int p = 0; p < 4; p++) {
            int idx = tid + p * 256;
            int r = idx >> 4, c = idx & 15;
            cpa16(ws_a + (uint32_t)(r * 272 + c * 16),
                  &A[(size_t)(o0 + r) * EXPD + k0 + c * 8]);
        }
#pragma unroll
        for (int p = 0; p < 4; p++) {
            int idx = tid + p * 256;
            int r = idx >> 3, c = idx & 7;
            cpa16(xs_a + (uint32_t)(r * 144 + c * 16),
                  &B[(size_t)(k0 + r) * HWN + n0 + c * 8]);
        }
        CP_COMMIT();
        CP_WAIT0();
        __syncthreads();

#pragma unroll
        for (int kk = 0; kk < 8; kk++) {
            uint32_t a0[4], a1[4], bb[4];
            ldsm4(a0, ws_a + a_off[0] + kk * 32);
            ldsm4(a1, ws_a + a_off[1] + kk * 32);
            ldsm4t(bb, xs_a + b_off + (uint32_t)kk * 2304);
            mma16(acc[0][0], a0, bb[0], bb[1]);
            mma16(acc[0][1], a0, bb[2], bb[3]);
            mma16(acc[1][0], a1, bb[0], bb[1]);
            mma16(acc[1][1], a1, bb[2], bb[3]);
        }
        __syncthreads();
    }

#pragma unroll
    for (int i = 0; i < 2; i++) {
        int ob = o0 + wo * 32 + i * 16 + g;
#pragma unroll
        for (int rr = 0; rr < 2; rr++) {
            int orow = ob + rr * 8;
            float bi = bias[orow];
#pragma unroll
            for (int j = 0; j < 2; j++) {
                int n = n0 + wn * 16 + j * 8 + 2 * t;
                size_t addr = (size_t)z * CDIM * HWN + (size_t)orow * HWN + n;
                float2 v = make_float2(acc[i][j][rr * 2 + 0] + bi,
                                       acc[i][j][rr * 2 + 1] + bi);
                float2 x2 = *(const float2*)&resid[addr];
                v.x += x2.x; v.y += x2.y;
                *(float2*)&C[addr] = v;
            }
        }
    }
}

// ---------------------------------------------------------------------------
// Monolithic attention, 256 threads, 2 CTAs/SM — PV skewed one km behind S.
// Per km: S-MMA(km) -> PV-MMA(km-1) [independent, fills tensor pipe] ->
//         exp(km)->pa [overlaps next km's ldsm/S]. Tail PV(3) per tile.
// Numerically identical to R11/R13.
// SMEM: Qs @0 (34816); Kb[2] @34816,52224; Vb[2] @69632,88064. Tot 106496.
// ---------------------------------------------------------------------------
__device__ __forceinline__ void s_half(float (&s0)[4], float (&s1)[4],
                                       const uint32_t (&qa)[8][4], uint32_t kb) {
    uint32_t k0[4], k1[4], k2[4], k3[4];
    ldsm4(k0, kb);
    ldsm4(k1, kb + 64);
    ldsm4(k2, kb + 128);
    ldsm4(k3, kb + 192);
    mma16(s0, qa[0], k0[0], k0[1]);
    mma16(s0, qa[1], k0[2], k0[3]);
    mma16(s0, qa[2], k1[0], k1[1]);
    mma16(s0, qa[3], k1[2], k1[3]);
    mma16(s1, qa[4], k2[0], k2[1]);
    mma16(s1, qa[5], k2[2], k2[3]);
    mma16(s1, qa[6], k3[0], k3[1]);
    mma16(s1, qa[7], k3[2], k3[3]);
}

__device__ __forceinline__ void pv_km(float (&oacc)[16][4], const uint32_t (&pa)[4],
                                      uint32_t vs, int km, int l7, int mi) {
#pragma unroll
    for (int d8p = 0; d8p < 8; d8p++) {
        uint32_t vv[4];
        ldsm4(vv, vs + (uint32_t)((d8p * 16 + (mi & 1) * 8 + l7) * 144
                                  + km * 32 + (mi >> 1) * 16));
        mma16(oacc[2 * d8p],     pa, vv[0], vv[2]);
        mma16(oacc[2 * d8p + 1], pa, vv[1], vv[3]);
    }
}

__global__ __launch_bounds__(256, 2) void attn_mma(
    const __nv_bfloat16* __restrict__ gq, const __nv_bfloat16* __restrict__ gk,
    const __nv_bfloat16* __restrict__ gv, __nv_bfloat16* __restrict__ gwsv)
{
    extern __shared__ __nv_bfloat16 smb[];
    const uint32_t sm_a = smem_u32(smb);

    const int tid = threadIdx.x;
    const int w = tid >> 5, lane = tid & 31;
    const int g = lane >> 2, t = lane & 3;
    const int l7 = lane & 7, mi = lane >> 3;
    const int b = blockIdx.z, h = blockIdx.y;
    const int bh = b * 4 + h;
    const int n0 = blockIdx.x * 128;
    const float CEXP = 0.08838834764831843f * 1.4426950408889634f;

    const __nv_bfloat16* Qg = gq + ((size_t)bh * HWN + n0) * CDIM;
    const __nv_bfloat16* Kg = gk + (size_t)bh * HWN * CDIM;
    const __nv_bfloat16* Vg = gv + (size_t)bh * CDIM * HWN;

#pragma unroll
    for (int p = 0; p < 8; p++) {
        int idx = tid + p * 256;
        int r = idx >> 4, c = idx & 15;
        cpa16(sm_a + (uint32_t)(r * 272 + c * 16), &Qg[(size_t)r * CDIM + c * 8]);
    }
    CP_COMMIT();
    CP_WAIT0();
    __syncthreads();

    uint32_t qa[8][4];
    {
        uint32_t qoff = sm_a + (uint32_t)((w * 16 + (mi & 1) * 8 + l7) * 272
                                          + (mi >> 1) * 16);
#pragma unroll
        for (int k = 0; k < 8; k++)
            ldsm4(qa[k], qoff + k * 32);
    }

#pragma unroll
    for (int p = 0; p < 4; p++) {
        int idx = tid + p * 256;
        int r = idx >> 4, c = idx & 15;
        cpa16(sm_a + (uint32_t)(34816 + r * 272 + c * 16),
              &Kg[(size_t)r * CDIM + c * 8]);
    }
#pragma unroll
    for (int p = 0; p < 4; p++) {
        int idx = tid + p * 256;
        int r = idx >> 3, c = idx & 7;
        cpa16(sm_a + (uint32_t)(69632 + r * 144 + c * 16),
              &Vg[(size_t)r * HWN + c * 8]);
    }
    CP_COMMIT();

    float oacc[16][4] = {};
    float rs0 = 0.f, rs1 = 0.f;

    for (int mt = 0; mt < 16; mt++) {
        CP_WAIT0();
        __syncthreads();

        if (mt + 1 < 16) {
            const int m0 = (mt + 1) * 64;
            const uint32_t kb = sm_a + (uint32_t)(34816 + ((mt + 1) & 1) * 17408);
            const uint32_t vb = sm_a + (uint32_t)(69632 + ((mt + 1) & 1) * 18432);
#pragma unroll
            for (int p = 0; p < 4; p++) {
                int idx = tid + p * 256;
                int r = idx >> 4, c = idx & 15;
                cpa16(kb + (uint32_t)(r * 272 + c * 16),
                      &Kg[(size_t)(m0 + r) * CDIM + c * 8]);
            }
#pragma unroll
            for (int p = 0; p < 4; p++) {
                int idx = tid + p * 256;
                int r = idx >> 3, c = idx & 7;
                cpa16(vb + (uint32_t)(r * 144 + c * 16),
                      &Vg[(size_t)r * HWN + m0 + c * 8]);
            }
            CP_COMMIT();
        }

        const uint32_t ks = sm_a + (uint32_t)(34816 + (mt & 1) * 17408);
        const uint32_t vs = sm_a + (uint32_t)(69632 + (mt & 1) * 18432);

        uint32_t pa[4];
#pragma unroll
        for (int km = 0; km < 4; km++) {
            // ---- S(km): 4 independent depth-4 chains ----
            const uint32_t kbA = ks + (uint32_t)((km * 16 + l7) * 272 + mi * 16);
            float sa0[4] = {0.f, 0.f, 0.f, 0.f}, sa1[4] = {0.f, 0.f, 0.f, 0.f};
            float sb0[4] = {0.f, 0.f, 0.f, 0.f}, sb1[4] = {0.f, 0.f, 0.f, 0.f};
            s_half(sa0, sa1, qa, kbA);
            s_half(sb0, sb1, qa, kbA + 8 * 272);

            // ---- PV(km-1): 16 independent MMAs fill the pipe while S lands ----
            if (km > 0)
                pv_km(oacc, pa, vs, km - 1, l7, mi);

            // ---- exp(km) -> pa (consumed next iteration / tail) ----
            float ea0 = ex2a((sa0[0] + sa1[0]) * CEXP);
            float ea1 = ex2a((sa0[1] + sa1[1]) * CEXP);
            float ea2 = ex2a((sa0[2] + sa1[2]) * CEXP);
            float ea3 = ex2a((sa0[3] + sa1[3]) * CEXP);
            float eb0 = ex2a((sb0[0] + sb1[0]) * CEXP);
            float eb1 = ex2a((sb0[1] + sb1[1]) * CEXP);
            float eb2 = ex2a((sb0[2] + sb1[2]) * CEXP);
            float eb3 = ex2a((sb0[3] + sb1[3]) * CEXP);
            rs0 += ea0 + ea1 + eb0 + eb1;
            rs1 += ea2 + ea3 + eb2 + eb3;
            pa[0] = packbf(ea0, ea1);
            pa[1] = packbf(ea2, ea3);
            pa[2] = packbf(eb0, eb1);
            pa[3] = packbf(eb2, eb3);
        }
        // ---- tail: PV(3) before the tile barrier ----
        pv_km(oacc, pa, vs, 3, l7, mi);
    }

    rs0 += __shfl_xor_sync(~0u, rs0, 1);
    rs0 += __shfl_xor_sync(~0u, rs0, 2);
    rs1 += __shfl_xor_sync(~0u, rs1, 1);
    rs1 += __shfl_xor_sync(~0u, rs1, 2);
    const float ri0 = 1.f / rs0, ri1 = 1.f / rs1;

    const int nA = n0 + w * 16 + g;
    const int nB = nA + 8;
    const size_t obA = ((size_t)b * EXPD + h * CDIM + (nA >> 3)) * HWN
                     + (size_t)(nA & 7) * CDIM;
    const size_t obB = ((size_t)b * EXPD + h * CDIM + (nB >> 3)) * HWN
                     + (size_t)(nB & 7) * CDIM;
#pragma unroll
    for (int d8 = 0; d8 < 16; d8++) {
        int d = d8 * 8 + 2 * t;
        *(uint32_t*)&gwsv[obA + d] = packbf(oacc[d8][0] * ri0,
                                            oacc[d8][1] * ri0);
        *(uint32_t*)&gwsv[obB + d] = packbf(oacc[d8][2] * ri1,
                                            oacc[d8][3] * ri1);
    }
}

// ---------------------------------------------------------------------------
extern "C" void kernel_launch(void* const* d_in, const int* in_sizes, int n_in,
                              void* d_out, int out_size)
{
    const float* x  = (const float*)d_in[0];
    const float* Wq = (const float*)d_in[1];
    const float* Wk = (const float*)d_in[2];
    const float* Wv = (const float*)d_in[3];
    const float* bv = (const float*)d_in[4];
    const float* Wt = (const float*)d_in[5];
    const float* bt = (const float*)d_in[6];
    float* out = (float*)d_out;

    __nv_bfloat16 *pq, *pk, *pv, *pw, *pxb, *pwq, *pwk, *pwv, *pwt;
    cudaGetSymbolAddress((void**)&pq, g_q);
    cudaGetSymbolAddress((void**)&pk, g_k);
    cudaGetSymbolAddress((void**)&pv, g_v);
    cudaGetSymbolAddress((void**)&pw, g_wsv);
    cudaGetSymbolAddress((void**)&pxb, g_xb);
    cudaGetSymbolAddress((void**)&pwq, g_wqb);
    cudaGetSymbolAddress((void**)&pwk, g_wkb);
    cudaGetSymbolAddress((void**)&pwv, g_wvb);
    cudaGetSymbolAddress((void**)&pwt, g_wtb);

    cvt_all<<<512, 256>>>(Wq, Wk, Wv, Wt, pwq, pwk, pwv, pwt);
    xpose<<<dim3(HWN / 32, CDIM / 32, NB), 256>>>(x, pxb);

    // Fused QKV projections, 64x128 CTA tile
    const int qkvsmem = 34816 + 2 * 17408;   // 69632 B
    cudaFuncSetAttribute(gemm_qkv, cudaFuncAttributeMaxDynamicSharedMemorySize,
                         qkvsmem);
    gemm_qkv<<<dim3(HWN / 128, EXPD / 64, NB), 256, qkvsmem>>>(
        pxb, pwq, pwk, pwv, bv, pq, pk, pv);

    // Monolithic attention, PV-skewed pipeline, 2 CTAs/SM
    const int asmem = 106496;
    cudaFuncSetAttribute(attn_mma, cudaFuncAttributeMaxDynamicSharedMemorySize,
                         asmem);
    attn_mma<<<dim3(8, 4, NB), 256, asmem>>>(pq, pk, pv, pw);

    // Output projection + bias + residual
    const int psmem = 17408 + 18432;  // 35840 B
    cudaFuncSetAttribute(gemm_proj, cudaFuncAttributeMaxDynamicSharedMemorySize,
                         psmem);
    gemm_proj<<<dim3(HWN / 64, CDIM / 64, NB), 256, psmem>>>(
        pwt, pw, bt, x, out);
}

// round 16
// speedup vs baseline: 1.1080x; 1.1080x over previous
#include <cuda_runtime.h>
#include <cuda_bf16.h>
#include <cstdint>

#define HWN 1024
#define CDIM 128
#define EXPD 512
#define NB   16

// Scratch (allocation-free rule: static __device__ arrays)
__device__ __align__(128) __nv_bfloat16 g_q[NB * EXPD * HWN]; // [b][h][n][d]
__device__ __align__(128) __nv_bfloat16 g_k[NB * EXPD * HWN]; // [b][h][m][d]
__device__ __align__(128) __nv_bfloat16 g_v[NB * EXPD * HWN]; // [b][h][d][m]
__device__ __align__(128) __nv_bfloat16 g_wsv[NB * EXPD * HWN]; // bf16 [b][c'][pix]
__device__ __align__(128) __nv_bfloat16 g_xb[NB * HWN * CDIM];  // x^T bf16 [b][n][c]
__device__ __align__(128) __nv_bfloat16 g_wqb[EXPD * CDIM];
__device__ __align__(128) __nv_bfloat16 g_wkb[EXPD * CDIM];
__device__ __align__(128) __nv_bfloat16 g_wvb[EXPD * CDIM];
__device__ __align__(128) __nv_bfloat16 g_wtb[CDIM * EXPD];

// ---------------------------------------------------------------------------
__device__ __forceinline__ uint32_t smem_u32(const void* p) {
    uint32_t a;
    asm("{ .reg .u64 t; cvta.to.shared.u64 t, %1; cvt.u32.u64 %0, t; }"
        : "=r"(a) : "l"(p));
    return a;
}

__device__ __forceinline__ void cpa16(uint32_t dst, const void* src) {
    asm volatile("cp.async.ca.shared.global [%0], [%1], 16;"
                 :: "r"(dst), "l"(src));
}
#define CP_COMMIT() asm volatile("cp.async.commit_group;")
#define CP_WAIT0()  asm volatile("cp.async.wait_group 0;")
#define CP_WAIT1()  asm volatile("cp.async.wait_group 1;")

// bf16 m16n8k16 mma
__device__ __forceinline__ void mma16(float (&d)[4], const uint32_t (&a)[4],
                                      uint32_t b0, uint32_t b1) {
    asm volatile(
        "mma.sync.aligned.m16n8k16.row.col.f32.bf16.bf16.f32 "
        "{%0,%1,%2,%3}, {%4,%5,%6,%7}, {%8,%9}, {%0,%1,%2,%3};"
        : "+f"(d[0]), "+f"(d[1]), "+f"(d[2]), "+f"(d[3])
        : "r"(a[0]), "r"(a[1]), "r"(a[2]), "r"(a[3]), "r"(b0), "r"(b1));
}

__device__ __forceinline__ void ldsm4(uint32_t (&r)[4], uint32_t addr) {
    asm volatile("ldmatrix.sync.aligned.m8n8.x4.shared.b16 {%0,%1,%2,%3}, [%4];"
                 : "=r"(r[0]), "=r"(r[1]), "=r"(r[2]), "=r"(r[3]) : "r"(addr));
}
__device__ __forceinline__ void ldsm4t(uint32_t (&r)[4], uint32_t addr) {
    asm volatile("ldmatrix.sync.aligned.m8n8.x4.trans.shared.b16 {%0,%1,%2,%3}, [%4];"
                 : "=r"(r[0]), "=r"(r[1]), "=r"(r[2]), "=r"(r[3]) : "r"(addr));
}

__device__ __forceinline__ uint32_t packbf(float lo, float hi) {
    uint32_t d;
    asm("cvt.rn.bf16x2.f32 %0, %1, %2;" : "=r"(d) : "f"(hi), "f"(lo));
    return d;
}

__device__ __forceinline__ float ex2a(float x) {
    float r;
    asm("ex2.approx.ftz.f32 %0, %1;" : "=f"(r) : "f"(x));
    return r;
}

// ---------------------------------------------------------------------------
// Merged prep: blocks [0,512) convert 4 weight matrices to bf16;
// blocks [512,2560) transpose x -> xb (bf16). One launch total.
__global__ __launch_bounds__(256) void prep(
    const float* __restrict__ Wq, const float* __restrict__ Wk,
    const float* __restrict__ Wv, const float* __restrict__ Wt,
    __nv_bfloat16* __restrict__ dq, __nv_bfloat16* __restrict__ dk,
    __nv_bfloat16* __restrict__ dv, __nv_bfloat16* __restrict__ dt,
    const float* __restrict__ x, __nv_bfloat16* __restrict__ xb)
{
    __shared__ float ts[32][33];
    if (blockIdx.x < 512) {
        const int seg = blockIdx.x >> 7;
        const int i = ((blockIdx.x & 127) * 256 + threadIdx.x) * 2;
        const float* s = (seg == 0) ? Wq : (seg == 1) ? Wk : (seg == 2) ? Wv : Wt;
        __nv_bfloat16* d = (seg == 0) ? dq : (seg == 1) ? dk : (seg == 2) ? dv : dt;
        float2 v = *(const float2*)&s[i];
        *(uint32_t*)&d[i] = packbf(v.x, v.y);
    } else {
        const int id = blockIdx.x - 512;            // 2048 blocks: 32 x 4 x 16
        const int nx = (id & 31) * 32;
        const int cy = ((id >> 5) & 3) * 32;
        const int z  = id >> 7;
        const int tx = threadIdx.x & 31, ty = threadIdx.x >> 5;
#pragma unroll
        for (int i = 0; i < 4; i++) {
            int c = cy + ty + i * 8;
            ts[ty + i * 8][tx] = x[((size_t)z * CDIM + c) * HWN + nx + tx];
        }
        __syncthreads();
#pragma unroll
        for (int i = 0; i < 4; i++) {
            int n = nx + ty + i * 8;
            xb[((size_t)z * HWN + n) * CDIM + cy + tx] =
                __float2bfloat16(ts[tx][ty + i * 8]);
        }
    }
}

// ---------------------------------------------------------------------------
// Fused QKV GEMM, bf16 m16n8k16, ldmatrix. CTA tile 64(o) x 128(n). (R13)
// ---------------------------------------------------------------------------
__global__ __launch_bounds__(256) void gemm_qkv(
    const __nv_bfloat16* __restrict__ xb,
    const __nv_bfloat16* __restrict__ Wqb, const __nv_bfloat16* __restrict__ Wkb,
    const __nv_bfloat16* __restrict__ Wvb, const float* __restrict__ bv,
    __nv_bfloat16* __restrict__ qo, __nv_bfloat16* __restrict__ ko,
    __nv_bfloat16* __restrict__ vo)
{
    extern __shared__ __nv_bfloat16 sb[];
    __nv_bfloat16* Xs = sb;                          // [128][136]
    __nv_bfloat16* WsA[2] = {sb + 17408, sb + 26112};// [64][136] each
    const uint32_t xs_a = smem_u32(Xs);
    const uint32_t ws_a[2] = {smem_u32(WsA[0]), smem_u32(WsA[1])};

    const int z = blockIdx.z;
    const int n0 = blockIdx.x * 128;
    const int o0 = blockIdx.y * 64;
    const int tid = threadIdx.x;
    const int w = tid >> 5, lane = tid & 31;
    const int g = lane >> 2, t = lane & 3;
    const int wo = w >> 2, wn = w & 3;
    const int l7 = lane & 7, mi = lane >> 3;

    uint32_t a_off[2], b_off[2];
#pragma unroll
    for (int i = 0; i < 2; i++)
        a_off[i] = (uint32_t)((wo * 32 + i * 16 + (mi & 1) * 8 + l7) * 272
                              + (mi >> 1) * 16);
#pragma unroll
    for (int i = 0; i < 2; i++)
        b_off[i] = (uint32_t)((wn * 32 + i * 16 + (mi >> 1) * 8 + l7) * 272
                              + (mi & 1) * 16);

    const __nv_bfloat16* Wmat[3] = {Wqb, Wkb, Wvb};
    const __nv_bfloat16* xrow = xb + ((size_t)z * HWN + n0) * CDIM;

#pragma unroll
    for (int p = 0; p < 8; p++) {
        int idx = tid + p * 256;
        int r = idx >> 4, c = idx & 15;
        cpa16(xs_a + (uint32_t)(r * 272 + c * 16), &xrow[(size_t)r * CDIM + c * 8]);
    }
#pragma unroll
    for (int p = 0; p < 4; p++) {
        int idx = tid + p * 256;
        int r = idx >> 4, c = idx & 15;
        cpa16(ws_a[0] + (uint32_t)(r * 272 + c * 16),
              &Wqb[(size_t)(o0 + r) * CDIM + c * 8]);
    }
    CP_COMMIT();

    for (int mat = 0; mat < 3; mat++) {
        if (mat < 2) {
            const __nv_bfloat16* Wn = Wmat[mat + 1];
#pragma unroll
            for (int p = 0; p < 4; p++) {
                int idx = tid + p * 256;
                int r = idx >> 4, c = idx & 15;
                cpa16(ws_a[(mat + 1) & 1] + (uint32_t)(r * 272 + c * 16),
                      &Wn[(size_t)(o0 + r) * CDIM + c * 8]);
            }
            CP_COMMIT();
            CP_WAIT1();
        } else {
            CP_WAIT0();
        }
        __syncthreads();

        const uint32_t wcur = ws_a[mat & 1];
        float acc[2][4][4] = {};
#pragma unroll
        for (int kk = 0; kk < 8; kk++) {
            uint32_t a0[4], a1[4], b0[4], b1[4];
            ldsm4(a0, wcur + a_off[0] + kk * 32);
            ldsm4(a1, wcur + a_off[1] + kk * 32);
            ldsm4(b0, xs_a + b_off[0] + kk * 32);
            ldsm4(b1, xs_a + b_off[1] + kk * 32);
            mma16(acc[0][0], a0, b0[0], b0[1]);
            mma16(acc[0][1], a0, b0[2], b0[3]);
            mma16(acc[0][2], a0, b1[0], b1[1]);
            mma16(acc[0][3], a0, b1[2], b1[3]);
            mma16(acc[1][0], a1, b0[0], b0[1]);
            mma16(acc[1][1], a1, b0[2], b0[3]);
            mma16(acc[1][2], a1, b1[0], b1[1]);
            mma16(acc[1][3], a1, b1[2], b1[3]);
        }
        __syncthreads();

        if (mat < 2) {
            __nv_bfloat16* C = (mat == 0) ? qo : ko;
            const int head = o0 >> 7, d0 = o0 & 127;
            float* Cs = (float*)WsA[mat & 1];
#pragma unroll
            for (int hh = 0; hh < 2; hh++) {
                if ((wn >> 1) == hh) {
#pragma unroll
                    for (int i = 0; i < 2; i++) {
                        int ol = wo * 32 + i * 16 + g;
#pragma unroll
                        for (int j = 0; j < 4; j++) {
                            int nl = (wn & 1) * 32 + j * 8 + 2 * t;
                            Cs[nl * 68 + ol]           = acc[i][j][0];
                            Cs[(nl + 1) * 68 + ol]     = acc[i][j][1];
                            Cs[nl * 68 + ol + 8]       = acc[i][j][2];
                            Cs[(nl + 1) * 68 + ol + 8] = acc[i][j][3];
                        }
                    }
                }
                __syncthreads();
#pragma unroll
                for (int p = 0; p < 4; p++) {
                    int idx = p * 256 + tid;
                    int nl = idx >> 4, o4 = (idx & 15) * 4;
                    float4 vv = *(float4*)&Cs[nl * 68 + o4];
                    uint2 pk = make_uint2(packbf(vv.x, vv.y), packbf(vv.z, vv.w));
                    *(uint2*)&C[(((size_t)z * 4 + head) * HWN + n0 + hh * 64 + nl)
                                * CDIM + d0 + o4] = pk;
                }
                __syncthreads();
            }
        } else {
#pragma unroll
            for (int i = 0; i < 2; i++) {
                int ob = o0 + wo * 32 + i * 16 + g;
#pragma unroll
                for (int rr = 0; rr < 2; rr++) {
                    int orow = ob + rr * 8;
                    float bi = bv[orow];
#pragma unroll
                    for (int j = 0; j < 4; j++) {
                        int n = n0 + wn * 32 + j * 8 + 2 * t;
                        size_t addr = (size_t)z * EXPD * HWN + (size_t)orow * HWN + n;
                        *(uint32_t*)&vo[addr] = packbf(acc[i][j][rr * 2 + 0] + bi,
                                                       acc[i][j][rr * 2 + 1] + bi);
                    }
                }
            }
        }
    }
}

// ---------------------------------------------------------------------------
// Projection GEMM, bf16 m16n8k16, CTA tile 64(o) x 128(n).
// A = Wtb [128][512] k-major (ldsm); B = wsv [k=512][n=1024] (ldsm.trans).
// SMEM: Ws [64][136] @0 (17408 B); Xs [128][136] @17408 (34816 B). Tot 52224.
// ---------------------------------------------------------------------------
__global__ __launch_bounds__(256) void gemm_proj(
    const __nv_bfloat16* __restrict__ A, const __nv_bfloat16* __restrict__ Bbase,
    const float* __restrict__ bias, const float* __restrict__ resid,
    float* __restrict__ C)
{
    extern __shared__ __nv_bfloat16 sb[];
    __nv_bfloat16* Ws = sb;            // [64][136]
    __nv_bfloat16* Xs = sb + 8704;     // [128][136]
    const uint32_t ws_a = smem_u32(Ws), xs_a = smem_u32(Xs);

    const int z = blockIdx.z;
    const __nv_bfloat16* B = Bbase + (size_t)z * EXPD * HWN;
    const int n0 = blockIdx.x * 128;
    const int o0 = blockIdx.y * 64;
    const int tid = threadIdx.x;
    const int w = tid >> 5, lane = tid & 31;
    const int g = lane >> 2, t = lane & 3;
    const int wo = w >> 2, wn = w & 3;
    const int l7 = lane & 7, mi = lane >> 3;

    uint32_t a_off[2];
#pragma unroll
    for (int i = 0; i < 2; i++)
        a_off[i] = (uint32_t)((wo * 32 + i * 16 + (mi & 1) * 8 + l7) * 272
                              + (mi >> 1) * 16);
    // trans B, two n-halves: row = kk*16 + (mi&1)*8 + l7 (stride 272 B),
    // col = wn*32 + i*16 + (mi>>1)*8
    uint32_t b_off[2];
#pragma unroll
    for (int i = 0; i < 2; i++)
        b_off[i] = (uint32_t)(((mi & 1) * 8 + l7) * 272
                              + (wn * 32 + i * 16 + (mi >> 1) * 8) * 2);

    float acc[2][4][4] = {};

    for (int k0 = 0; k0 < EXPD; k0 += 128) {
#pragma unroll
        for (int p = 0; p < 4; p++) {
            int idx = tid + p * 256;
            int r = idx >> 4, c = idx & 15;
            cpa16(ws_a + (uint32_t)(r * 272 + c * 16),
                  &A[(size_t)(o0 + r) * EXPD + k0 + c * 8]);
        }
#pragma unroll
        for (int p = 0; p < 8; p++) {
            int idx = tid + p * 256;
            int r = idx >> 4, c = idx & 15;
            cpa16(xs_a + (uint32_t)(r * 272 + c * 16),
                  &B[(size_t)(k0 + r) * HWN + n0 + c * 8]);
        }
        CP_COMMIT();
        CP_WAIT0();
        __syncthreads();

#pragma unroll
        for (int kk = 0; kk < 8; kk++) {
            uint32_t a0[4], a1[4], bb0[4], bb1[4];
            ldsm4(a0, ws_a + a_off[0] + kk * 32);
            ldsm4(a1, ws_a + a_off[1] + kk * 32);
            ldsm4t(bb0, xs_a + b_off[0] + (uint32_t)kk * 4352);  // 16 rows * 272 B
            ldsm4t(bb1, xs_a + b_off[1] + (uint32_t)kk * 4352);
            mma16(acc[0][0], a0, bb0[0], bb0[1]);
            mma16(acc[0][1], a0, bb0[2], bb0[3]);
            mma16(acc[0][2], a0, bb1[0], bb1[1]);
            mma16(acc[0][3], a0, bb1[2], bb1[3]);
            mma16(acc[1][0], a1, bb0[0], bb0[1]);
            mma16(acc[1][1], a1, bb0[2], bb0[3]);
            mma16(acc[1][2], a1, bb1[0], bb1[1]);
            mma16(acc[1][3], a1, bb1[2], bb1[3]);
        }
        __syncthreads();
    }

#pragma unroll
    for (int i = 0; i < 2; i++) {
        int ob = o0 + wo * 32 + i * 16 + g;
#pragma unroll
        for (int rr = 0; rr < 2; rr++) {
            int orow = ob + rr * 8;
            float bi = bias[orow];
#pragma unroll
            for (int j = 0; j < 4; j++) {
                int n = n0 + wn * 32 + j * 8 + 2 * t;
                size_t addr = (size_t)z * CDIM * HWN + (size_t)orow * HWN + n;
                float2 v = make_float2(acc[i][j][rr * 2 + 0] + bi,
                                       acc[i][j][rr * 2 + 1] + bi);
                float2 x2 = *(const float2*)&resid[addr];
                v.x += x2.x; v.y += x2.y;
                *(float2*)&C[addr] = v;
            }
        }
    }
}

// ---------------------------------------------------------------------------
// Monolithic attention (R13-benched version, byte-for-byte): 256 threads,
// 2 CTAs/SM. SMEM: Qs @0 (34816); Kb[2] @34816,52224; Vb[2] @69632,88064.
// ---------------------------------------------------------------------------
__global__ __launch_bounds__(256, 2) void attn_mma(
    const __nv_bfloat16* __restrict__ gq, const __nv_bfloat16* __restrict__ gk,
    const __nv_bfloat16* __restrict__ gv, __nv_bfloat16* __restrict__ gwsv)
{
    extern __shared__ __nv_bfloat16 smb[];
    const uint32_t sm_a = smem_u32(smb);

    const int tid = threadIdx.x;
    const int w = tid >> 5, lane = tid & 31;
    const int g = lane >> 2, t = lane & 3;
    const int l7 = lane & 7, mi = lane >> 3;
    const int b = blockIdx.z, h = blockIdx.y;
    const int bh = b * 4 + h;
    const int n0 = blockIdx.x * 128;
    const float CEXP = 0.08838834764831843f * 1.4426950408889634f;

    const __nv_bfloat16* Qg = gq + ((size_t)bh * HWN + n0) * CDIM;
    const __nv_bfloat16* Kg = gk + (size_t)bh * HWN * CDIM;
    const __nv_bfloat16* Vg = gv + (size_t)bh * CDIM * HWN;

#pragma unroll
    for (int p = 0; p < 8; p++) {
        int idx = tid + p * 256;
        int r = idx >> 4, c = idx & 15;
        cpa16(sm_a + (uint32_t)(r * 272 + c * 16), &Qg[(size_t)r * CDIM + c * 8]);
    }
    CP_COMMIT();
    CP_WAIT0();
    __syncthreads();

    uint32_t qa[8][4];
    {
        uint32_t qoff = sm_a + (uint32_t)((w * 16 + (mi & 1) * 8 + l7) * 272
                                          + (mi >> 1) * 16);
#pragma unroll
        for (int k = 0; k < 8; k++)
            ldsm4(qa[k], qoff + k * 32);
    }

#pragma unroll
    for (int p = 0; p < 4; p++) {
        int idx = tid + p * 256;
        int r = idx >> 4, c = idx & 15;
        cpa16(sm_a + (uint32_t)(34816 + r * 272 + c * 16),
              &Kg[(size_t)r * CDIM + c * 8]);
    }
#pragma unroll
    for (int p = 0; p < 4; p++) {
        int idx = tid + p * 256;
        int r = idx >> 3, c = idx & 7;
        cpa16(sm_a + (uint32_t)(69632 + r * 144 + c * 16),
              &Vg[(size_t)r * HWN + c * 8]);
    }
    CP_COMMIT();

    float oacc[16][4] = {};
    float rs0 = 0.f, rs1 = 0.f;

    for (int mt = 0; mt < 16; mt++) {
        CP_WAIT0();
        __syncthreads();

        if (mt + 1 < 16) {
            const int m0 = (mt + 1) * 64;
            const uint32_t kb = sm_a + (uint32_t)(34816 + ((mt + 1) & 1) * 17408);
            const uint32_t vb = sm_a + (uint32_t)(69632 + ((mt + 1) & 1) * 18432);
#pragma unroll
            for (int p = 0; p < 4; p++) {
                int idx = tid + p * 256;
                int r = idx >> 4, c = idx & 15;
                cpa16(kb + (uint32_t)(r * 272 + c * 16),
                      &Kg[(size_t)(m0 + r) * CDIM + c * 8]);
            }
#pragma unroll
            for (int p = 0; p < 4; p++) {
                int idx = tid + p * 256;
                int r = idx >> 3, c = idx & 7;
                cpa16(vb + (uint32_t)(r * 144 + c * 16),
                      &Vg[(size_t)r * HWN + m0 + c * 8]);
            }
            CP_COMMIT();
        }

        const uint32_t ks = sm_a + (uint32_t)(34816 + (mt & 1) * 17408);
        const uint32_t vs = sm_a + (uint32_t)(69632 + (mt & 1) * 18432);

#pragma unroll
        for (int km = 0; km < 4; km++) {
            const uint32_t kbA = ks + (uint32_t)((km * 16 + l7) * 272 + mi * 16);
            const uint32_t kbB = kbA + 8 * 272;
            uint32_t k0[4], k1[4], k2[4], k3[4];
            float sa0[4] = {0.f, 0.f, 0.f, 0.f}, sa1[4] = {0.f, 0.f, 0.f, 0.f};
            float sb0[4] = {0.f, 0.f, 0.f, 0.f}, sb1[4] = {0.f, 0.f, 0.f, 0.f};
            ldsm4(k0, kbA);
            ldsm4(k1, kbA + 64);
            ldsm4(k2, kbA + 128);
            ldsm4(k3, kbA + 192);
            mma16(sa0, qa[0], k0[0], k0[1]);
            mma16(sa0, qa[1], k0[2], k0[3]);
            mma16(sa0, qa[2], k1[0], k1[1]);
            mma16(sa0, qa[3], k1[2], k1[3]);
            mma16(sa1, qa[4], k2[0], k2[1]);
            mma16(sa1, qa[5], k2[2], k2[3]);
            mma16(sa1, qa[6], k3[0], k3[1]);
            mma16(sa1, qa[7], k3[2], k3[3]);
            ldsm4(k0, kbB);
            ldsm4(k1, kbB + 64);
            ldsm4(k2, kbB + 128);
            ldsm4(k3, kbB + 192);
            mma16(sb0, qa[0], k0[0], k0[1]);
            mma16(sb0, qa[1], k0[2], k0[3]);
            mma16(sb0, qa[2], k1[0], k1[1]);
            mma16(sb0, qa[3], k1[2], k1[3]);
            mma16(sb1, qa[4], k2[0], k2[1]);
            mma16(sb1, qa[5], k2[2], k2[3]);
            mma16(sb1, qa[6], k3[0], k3[1]);
            mma16(sb1, qa[7], k3[2], k3[3]);

            float ea0 = ex2a((sa0[0] + sa1[0]) * CEXP);
            float ea1 = ex2a((sa0[1] + sa1[1]) * CEXP);
            float ea2 = ex2a((sa0[2] + sa1[2]) * CEXP);
            float ea3 = ex2a((sa0[3] + sa1[3]) * CEXP);
            float eb0 = ex2a((sb0[0] + sb1[0]) * CEXP);
            float eb1 = ex2a((sb0[1] + sb1[1]) * CEXP);
            float eb2 = ex2a((sb0[2] + sb1[2]) * CEXP);
            float eb3 = ex2a((sb0[3] + sb1[3]) * CEXP);
            rs0 += ea0 + ea1 + eb0 + eb1;
            rs1 += ea2 + ea3 + eb2 + eb3;
            uint32_t pa[4];
            pa[0] = packbf(ea0, ea1);
            pa[1] = packbf(ea2, ea3);
            pa[2] = packbf(eb0, eb1);
            pa[3] = packbf(eb2, eb3);

#pragma unroll
            for (int d8p = 0; d8p < 8; d8p++) {
                uint32_t vv[4];
                ldsm4(vv, vs + (uint32_t)((d8p * 16 + (mi & 1) * 8 + l7) * 144
                                          + km * 32 + (mi >> 1) * 16));
                mma16(oacc[2 * d8p],     pa, vv[0], vv[2]);
                mma16(oacc[2 * d8p + 1], pa, vv[1], vv[3]);
            }
        }
    }

    rs0 += __shfl_xor_sync(~0u, rs0, 1);
    rs0 += __shfl_xor_sync(~0u, rs0, 2);
    rs1 += __shfl_xor_sync(~0u, rs1, 1);
    rs1 += __shfl_xor_sync(~0u, rs1, 2);
    const float ri0 = 1.f / rs0, ri1 = 1.f / rs1;

    const int nA = n0 + w * 16 + g;
    const int nB = nA + 8;
    const size_t obA = ((size_t)b * EXPD + h * CDIM + (nA >> 3)) * HWN
                     + (size_t)(nA & 7) * CDIM;
    const size_t obB = ((size_t)b * EXPD + h * CDIM + (nB >> 3)) * HWN
                     + (size_t)(nB & 7) * CDIM;
#pragma unroll
    for (int d8 = 0; d8 < 16; d8++) {
        int d = d8 * 8 + 2 * t;
        *(uint32_t*)&gwsv[obA + d] = packbf(oacc[d8][0] * ri0,
                                            oacc[d8][1] * ri0);
        *(uint32_t*)&gwsv[obB + d] = packbf(oacc[d8][2] * ri1,
                                            oacc[d8][3] * ri1);
    }
}

// ---------------------------------------------------------------------------
extern "C" void kernel_launch(void* const* d_in, const int* in_sizes, int n_in,
                              void* d_out, int out_size)
{
    const float* x  = (const float*)d_in[0];
    const float* Wq = (const float*)d_in[1];
    const float* Wk = (const float*)d_in[2];
    const float* Wv = (const float*)d_in[3];
    const float* bv = (const float*)d_in[4];
    const float* Wt = (const float*)d_in[5];
    const float* bt = (const float*)d_in[6];
    float* out = (float*)d_out;

    __nv_bfloat16 *pq, *pk, *pv, *pw, *pxb, *pwq, *pwk, *pwv, *pwt;
    cudaGetSymbolAddress((void**)&pq, g_q);
    cudaGetSymbolAddress((void**)&pk, g_k);
    cudaGetSymbolAddress((void**)&pv, g_v);
    cudaGetSymbolAddress((void**)&pw, g_wsv);
    cudaGetSymbolAddress((void**)&pxb, g_xb);
    cudaGetSymbolAddress((void**)&pwq, g_wqb);
    cudaGetSymbolAddress((void**)&pwk, g_wkb);
    cudaGetSymbolAddress((void**)&pwv, g_wvb);
    cudaGetSymbolAddress((void**)&pwt, g_wtb);

    // Merged weight-cvt + x-transpose
    prep<<<2560, 256>>>(Wq, Wk, Wv, Wt, pwq, pwk, pwv, pwt, x, pxb);

    // Fused QKV projections, 64x128 CTA tile
    const int qkvsmem = 34816 + 2 * 17408;   // 69632 B
    cudaFuncSetAttribute(gemm_qkv, cudaFuncAttributeMaxDynamicSharedMemorySize,
                         qkvsmem);
    gemm_qkv<<<dim3(HWN / 128, EXPD / 64, NB), 256, qkvsmem>>>(
        pxb, pwq, pwk, pwv, bv, pq, pk, pv);

    // Monolithic attention (R13), 2 CTAs/SM
    const int asmem = 106496;
    cudaFuncSetAttribute(attn_mma, cudaFuncAttributeMaxDynamicSharedMemorySize,
                         asmem);
    attn_mma<<<dim3(8, 4, NB), 256, asmem>>>(pq, pk, pv, pw);

    // Output projection, 64x128 CTA tile
    const int psmem = 17408 + 34816;  // 52224 B
    cudaFuncSetAttribute(gemm_proj, cudaFuncAttributeMaxDynamicSharedMemorySize,
                         psmem);
    gemm_proj<<<dim3(HWN / 128, CDIM / 64, NB), 256, psmem>>>(
        pwt, pw, bt, x, out);
}